// round 15
// baseline (speedup 1.0000x reference)
#include <cuda_runtime.h>

#define B_ 8
#define H_ 352
#define W_ 1216
#define PLANE (H_*W_)
#define NPIX (B_*PLANE)
#define NCHUNK 38                   // W_/32 horizontal chunks
#define NCHV 11                     // H_/32 vertical chunks
#define SPAN 14                     // interior chunks per hscan block
#define NWARPS 16                   // hscan warps (SPAN + 2 halo)

// Vertical partials (aw, awd), normal (b,h,w) layout.
__device__ float2 PV[NPIX];

__device__ __forceinline__ float wsum(float x, int lane) {
    #pragma unroll
    for (int d = 1; d < 32; d <<= 1) {
        float o = __shfl_up_sync(0xFFFFFFFFu, x, d);
        if (lane >= d) x += o;
    }
    return x;
}

// ---------------------------------------------------------------------------
// Vertical O(1) scan. Block = 8 warps x 8 adjacent columns. Double-buffered
// input tile + staging tile -> 2 barriers per chunk. S arrays warp-private.
// ---------------------------------------------------------------------------
__global__ void __launch_bounds__(256)
vscan_kernel(const float* __restrict__ pred_log,
             const int*   __restrict__ mask,
             const float* __restrict__ var,
             const float* __restrict__ depth)
{
    __shared__ float S0[8][3][33], S1[8][3][33], G0[8][3][33], G1[8][3][33];
    __shared__ float  s_e[2][32][9];
    __shared__ float2 s_a[2][32][9];   // (g2, g2*d)
    __shared__ float2 s_b[2][32][9];   // (g3, g3*d)
    __shared__ float2 ST[2][32][9];    // staging, padded

    const int lane = threadIdx.x, wp = threadIdx.y;
    const int t  = wp * 32 + lane;
    const int hl = t >> 3, wl = t & 7;
    const int b  = blockIdx.y, w0 = blockIdx.x * 8;

    const float* pvp = pred_log + (size_t)b * 2 * PLANE + PLANE;
    const float* v2p = var   + (size_t)b * 4 * PLANE + 2 * PLANE;
    const float* v3p = var   + (size_t)b * 4 * PLANE + 3 * PLANE;
    const float* dp  = depth + (size_t)b * PLANE;
    const int*   mp  = mask  + (size_t)b * PLANE;

    // slot 2 = chunk -1 (zero)
    S0[wp][2][lane + 1] = 0.f; S1[wp][2][lane + 1] = 0.f;
    G0[wp][2][lane + 1] = 0.f; G1[wp][2][lane + 1] = 0.f;
    if (lane == 0) { S0[wp][2][0] = 0.f; S1[wp][2][0] = 0.f;
                     G0[wp][2][0] = 0.f; G1[wp][2][0] = 0.f; }

#define LOAD_TILE(c, tb) do {                               \
        size_t p = (size_t)((c) * 32 + hl) * W_ + w0 + wl;  \
        float pv = pvp[p];                                  \
        float m  = mp[p] ? 1.f : 0.f;                       \
        float g2 = __expf(-fminf(v2p[p], 5.f)) * m;         \
        float g3 = __expf(-fminf(v3p[p], 5.f)) * m;         \
        float dd = dp[p];                                   \
        s_e[tb][hl][wl] = __expf(pv);                       \
        s_a[tb][hl][wl] = make_float2(g2, g2 * dd);         \
        s_b[tb][hl][wl] = make_float2(g3, g3 * dd);         \
    } while (0)

#define SCAN_SLOT(sl, tb, QEX, QT, BM) do {                              \
        float  e  = s_e[tb][lane][wp];                                   \
        float2 fa = s_a[tb][lane][wp];                                   \
        float2 fb = s_b[tb][lane][wp];                                   \
        BM = __ballot_sync(0xFFFFFFFFu, fa.x > 0.f);                     \
        float q = e;                                                     \
        _Pragma("unroll")                                                \
        for (int dd = 1; dd < 32; dd <<= 1) {                            \
            float o = __shfl_up_sync(0xFFFFFFFFu, q, dd);                \
            if (lane >= dd) q *= o;                                      \
        }                                                                \
        QT  = __shfl_sync(0xFFFFFFFFu, q, 31);                           \
        QEX = __shfl_up_sync(0xFFFFFFFFu, q, 1);                         \
        if (lane == 0) QEX = 1.f;                                        \
        float rq = __fdividef(1.f, QEX);                                 \
        S0[wp][sl][lane + 1] = wsum(fa.y * rq, lane);                    \
        S1[wp][sl][lane + 1] = wsum(fb.y * rq, lane);                    \
        G0[wp][sl][lane + 1] = wsum(fa.x, lane);                         \
        G1[wp][sl][lane + 1] = wsum(fb.x, lane);                         \
        if (lane == 0) { S0[wp][sl][0] = 0.f; S1[wp][sl][0] = 0.f;       \
                         G0[wp][sl][0] = 0.f; G1[wp][sl][0] = 0.f; }     \
        __syncwarp();                                                    \
    } while (0)

    float qex_c, qt_c, qt_p = 1.f, qex_n, qt_n;
    unsigned bm_p = 0u, bm_c, bm_n;

    LOAD_TILE(0, 0);
    __syncthreads();
    SCAN_SLOT(0, 0, qex_c, qt_c, bm_c);

    for (int c = 0; c < NCHV; ++c) {
        int sn = (c + 1) % 3;
        if (c + 1 < NCHV) {
            LOAD_TILE(c + 1, (c + 1) & 1);
            __syncthreads();                       // tile (c+1) ready
            SCAN_SLOT(sn, (c + 1) & 1, qex_n, qt_n, bm_n);
        } else {
            S0[wp][sn][lane + 1] = 0.f; S1[wp][sn][lane + 1] = 0.f;
            G0[wp][sn][lane + 1] = 0.f; G1[wp][sn][lane + 1] = 0.f;
            if (lane == 0) { S0[wp][sn][0] = 0.f; S1[wp][sn][0] = 0.f;
                             G0[wp][sn][0] = 0.f; G1[wp][sn][0] = 0.f; }
            qex_n = 1.f; qt_n = 1.f; bm_n = 0u;
            __syncwarp();
        }

        int sp = (c + 2) % 3, sc = c % 3;
        unsigned u = __funnelshift_r(bm_p, bm_c, lane);
        int lim0 = __clz(~u);
        unsigned v = (lane == 31) ? bm_n : __funnelshift_r(bm_c, bm_n, lane + 1);
        unsigned nv = ~v;
        int lim1 = nv ? (__ffs(nv) - 1) : 32;

        int l0c = min(lim0, lane);      int ex0 = lim0 - l0c;
        int l1c = min(lim1, 31 - lane); int ex1 = lim1 - l1c;

        float sum = (S0[wp][sc][lane] - S0[wp][sc][lane - l0c])
                  + (S1[wp][sc][lane + 1 + l1c] - S1[wp][sc][lane + 1]);
        float sg  = (G0[wp][sc][lane] - G0[wp][sc][lane - l0c])
                  + (G1[wp][sc][lane + 1 + l1c] - G1[wp][sc][lane + 1]);
        if (ex0 > 0) {
            sum += qt_p * (S0[wp][sp][32] - S0[wp][sp][32 - ex0]);
            sg  += G0[wp][sp][32] - G0[wp][sp][32 - ex0];
        }
        if (ex1 > 0) {
            sum += __fdividef(S1[wp][sn][ex1], qt_c);
            sg  += G1[wp][sn][ex1];
        }
        ST[c & 1][lane][wp] = make_float2(sg, qex_c * sum);
        __syncthreads();                           // ST[c&1] complete
        PV[((size_t)b * H_ + c * 32 + hl) * W_ + w0 + wl] = ST[c & 1][hl][wl];

        bm_p = bm_c; bm_c = bm_n; qt_p = qt_c; qt_c = qt_n; qex_c = qex_n;
    }
#undef LOAD_TILE
#undef SCAN_SLOT
}

// ---------------------------------------------------------------------------
// Horizontal O(1) scan: 16 warps scan 16 chunks (14 interior + 2 halo) of one
// row from raw inputs; warps 0..13 resolve pixels, combine PV, blend, write.
// ---------------------------------------------------------------------------
__global__ void __launch_bounds__(512)
hscan_kernel(const float* __restrict__ pred_log,
             const int*   __restrict__ mask,
             const float* __restrict__ var,
             const float* __restrict__ depthin,
             const float* __restrict__ lam_p,
             float*       __restrict__ out)
{
    __shared__ float S0[NWARPS][33], S1[NWARPS][33], G0[NWARPS][33], G1[NWARPS][33];
    __shared__ float QX[NWARPS][32];
    __shared__ float QT[NWARPS];
    __shared__ unsigned BMs[NWARPS];

    const int row  = blockIdx.y;            // b*H_ + h
    const int b    = row / H_;
    const int span = blockIdx.x;
    const int lane = threadIdx.x, k = threadIdx.y;
    const int c = span * SPAN + k - 1;

    const size_t rowoff  = (size_t)row * W_;
    const size_t inplane = rowoff - (size_t)b * PLANE;

    float e0 = 1.f, g0 = 0.f, g1 = 0.f, d = 0.f;
    if (c >= 0 && c < NCHUNK) {
        int col = c * 32 + lane;
        size_t p = inplane + col;
        float ph = pred_log[(size_t)b * 2 * PLANE + p];
        float m  = mask[rowoff + col] ? 1.f : 0.f;
        float v0 = var[(size_t)b * 4 * PLANE + p];
        float v1 = var[(size_t)b * 4 * PLANE + PLANE + p];
        d  = depthin[rowoff + col];
        e0 = __expf(ph);
        g0 = __expf(-fminf(v0, 5.f)) * m;
        g1 = __expf(-fminf(v1, 5.f)) * m;
    }
    unsigned bm = __ballot_sync(0xFFFFFFFFu, g0 > 0.f);

    float q = e0;
    #pragma unroll
    for (int dd = 1; dd < 32; dd <<= 1) {
        float o = __shfl_up_sync(0xFFFFFFFFu, q, dd);
        if (lane >= dd) q *= o;
    }
    float qtot = __shfl_sync(0xFFFFFFFFu, q, 31);
    float qex  = __shfl_up_sync(0xFFFFFFFFu, q, 1);
    if (lane == 0) qex = 1.f;
    float rq = __fdividef(1.f, qex);

    S0[k][lane + 1] = wsum(g0 * d * rq, lane);
    S1[k][lane + 1] = wsum(g1 * d * rq, lane);
    G0[k][lane + 1] = wsum(g0, lane);
    G1[k][lane + 1] = wsum(g1, lane);
    QX[k][lane] = qex;
    if (lane == 0) {
        S0[k][0] = 0.f; S1[k][0] = 0.f; G0[k][0] = 0.f; G1[k][0] = 0.f;
        QT[k] = qtot;  BMs[k] = bm;
    }
    __syncthreads();

    if (k >= SPAN) return;
    const int s  = k + 1;
    const int cc = span * SPAN + k;
    if (cc >= NCHUNK) return;
    const int jl = lane;
    const size_t idx = rowoff + cc * 32 + jl;

    float din = depthin[idx];
    unsigned bmc = BMs[s];
    if (!((bmc >> jl) & 1u)) { out[idx] = din; return; }

    float2 pv = PV[idx];
    unsigned bmp = BMs[s - 1], bmn = BMs[s + 1];
    unsigned u = __funnelshift_r(bmp, bmc, jl);
    int lim0 = __clz(~u);
    unsigned v = (jl == 31) ? bmn : __funnelshift_r(bmc, bmn, jl + 1);
    unsigned nv = ~v;
    int lim1 = nv ? (__ffs(nv) - 1) : 32;

    int l0c = min(lim0, jl);        int ex0 = lim0 - l0c;
    int l1c = min(lim1, 31 - jl);   int ex1 = lim1 - l1c;

    float aw  = pv.x;
    float awd = pv.y;
    float qj  = QX[s][jl];

    float sum = S0[s][jl] - S0[s][jl - l0c];
    float sg  = G0[s][jl] - G0[s][jl - l0c];
    if (ex0 > 0) {
        sum += QT[s - 1] * (S0[s - 1][32] - S0[s - 1][32 - ex0]);
        sg  += G0[s - 1][32] - G0[s - 1][32 - ex0];
    }
    sum += S1[s][jl + 1 + l1c] - S1[s][jl + 1];
    sg  += G1[s][jl + 1 + l1c] - G1[s][jl + 1];
    if (ex1 > 0) {
        sum += __fdividef(S1[s + 1][ex1], QT[s]);
        sg  += G1[s + 1][ex1];
    }
    aw  += sg;
    awd += qj * sum;

    float o = din;
    if (aw > 0.f) {
        float lat = awd / fmaxf(aw, 1e-12f);
        if (lat > 0.f) {
            float lam = lam_p[0];
            o = din * (1.f - lam) + lat * lam;
        }
    }
    out[idx] = o;
}

extern "C" void kernel_launch(void* const* d_in, const int* in_sizes, int n_in,
                              void* d_out, int out_size)
{
    const float* pred_log = (const float*)d_in[0];
    const int*   mask     = (const int*)  d_in[1];
    const float* variance = (const float*)d_in[2];
    const float* depthin  = (const float*)d_in[3];
    const float* lam      = (const float*)d_in[4];
    float* out = (float*)d_out;

    dim3 blkv(32, 8);
    dim3 gv(W_ / 8, B_);                            // 152 x 8
    vscan_kernel<<<gv, blkv>>>(pred_log, mask, variance, depthin);

    dim3 blkh(32, NWARPS);
    dim3 gh((NCHUNK + SPAN - 1) / SPAN, B_ * H_);   // 3 x 2816
    hscan_kernel<<<gh, blkh>>>(pred_log, mask, variance, depthin, lam, out);
}

// round 16
// speedup vs baseline: 1.0842x; 1.0842x over previous
#include <cuda_runtime.h>

#define B_ 8
#define H_ 352
#define W_ 1216
#define PLANE (H_*W_)
#define NPIX (B_*PLANE)
#define NCHUNK 38                   // W_/32 horizontal chunks
#define NCHV 11                     // H_/32 vertical chunks
#define SPAN 14                     // interior chunks per hscan block
#define NWARPS 16                   // hscan warps (SPAN + 2 halo)

// Vertical partials (aw, awd), normal (b,h,w) layout.
__device__ float2 PV[NPIX];

__device__ __forceinline__ float wsum(float x, int lane) {
    #pragma unroll
    for (int d = 1; d < 32; d <<= 1) {
        float o = __shfl_up_sync(0xFFFFFFFFu, x, d);
        if (lane >= d) x += o;
    }
    return x;
}

// ---------------------------------------------------------------------------
// Vertical O(1) scan (R14-proven). Block = 8 warps x 8 adjacent columns.
// Per h-chunk: cooperative coalesced raw-input tile load -> smem, per-warp
// column scan (shared anchored product), O(1) window resolve, coalesced PV.
// ---------------------------------------------------------------------------
__global__ void __launch_bounds__(256)
vscan_kernel(const float* __restrict__ pred_log,
             const int*   __restrict__ mask,
             const float* __restrict__ var,
             const float* __restrict__ depth)
{
    __shared__ float S0[8][3][33], S1[8][3][33], G0[8][3][33], G1[8][3][33];
    __shared__ float s_e[32][9], s_g2[32][9], s_gd2[32][9], s_g3[32][9], s_gd3[32][9];
    __shared__ float2 ST[32][8];

    const int lane = threadIdx.x, wp = threadIdx.y;
    const int t  = wp * 32 + lane;
    const int hl = t >> 3, wl = t & 7;          // tile-load coords
    const int b  = blockIdx.y, w0 = blockIdx.x * 8;

    const float* pvp = pred_log + (size_t)b * 2 * PLANE + PLANE;
    const float* v2p = var   + (size_t)b * 4 * PLANE + 2 * PLANE;
    const float* v3p = var   + (size_t)b * 4 * PLANE + 3 * PLANE;
    const float* dp  = depth + (size_t)b * PLANE;
    const int*   mp  = mask  + (size_t)b * PLANE;

    // slot 2 = chunk -1 (zero)
    S0[wp][2][lane + 1] = 0.f; S1[wp][2][lane + 1] = 0.f;
    G0[wp][2][lane + 1] = 0.f; G1[wp][2][lane + 1] = 0.f;
    if (lane == 0) { S0[wp][2][0] = 0.f; S1[wp][2][0] = 0.f;
                     G0[wp][2][0] = 0.f; G1[wp][2][0] = 0.f; }

#define LOAD_TILE(c) do {                                   \
        size_t p = (size_t)((c) * 32 + hl) * W_ + w0 + wl;  \
        float pv = pvp[p];                                  \
        float m  = mp[p] ? 1.f : 0.f;                       \
        float g2 = __expf(-fminf(v2p[p], 5.f)) * m;         \
        float g3 = __expf(-fminf(v3p[p], 5.f)) * m;         \
        float dd = dp[p];                                   \
        s_e [hl][wl] = __expf(pv);                          \
        s_g2[hl][wl] = g2;  s_gd2[hl][wl] = g2 * dd;        \
        s_g3[hl][wl] = g3;  s_gd3[hl][wl] = g3 * dd;        \
    } while (0)

#define SCAN_SLOT(sl, QEX, QT, BM) do {                                  \
        float e  = s_e [lane][wp];                                       \
        float ga = s_g2[lane][wp], gda = s_gd2[lane][wp];                \
        float gb = s_g3[lane][wp], gdb = s_gd3[lane][wp];                \
        BM = __ballot_sync(0xFFFFFFFFu, ga > 0.f);                       \
        float q = e;                                                     \
        _Pragma("unroll")                                                \
        for (int dd = 1; dd < 32; dd <<= 1) {                            \
            float o = __shfl_up_sync(0xFFFFFFFFu, q, dd);                \
            if (lane >= dd) q *= o;                                      \
        }                                                                \
        QT  = __shfl_sync(0xFFFFFFFFu, q, 31);                           \
        QEX = __shfl_up_sync(0xFFFFFFFFu, q, 1);                         \
        if (lane == 0) QEX = 1.f;                                        \
        float rq = __fdividef(1.f, QEX);                                 \
        S0[wp][sl][lane + 1] = wsum(gda * rq, lane);                     \
        S1[wp][sl][lane + 1] = wsum(gdb * rq, lane);                     \
        G0[wp][sl][lane + 1] = wsum(ga, lane);                           \
        G1[wp][sl][lane + 1] = wsum(gb, lane);                           \
        if (lane == 0) { S0[wp][sl][0] = 0.f; S1[wp][sl][0] = 0.f;       \
                         G0[wp][sl][0] = 0.f; G1[wp][sl][0] = 0.f; }     \
        __syncwarp();                                                    \
    } while (0)

    float qex_c, qt_c, qt_p = 1.f, qex_n, qt_n;
    unsigned bm_p = 0u, bm_c, bm_n;

    LOAD_TILE(0);
    __syncthreads();
    SCAN_SLOT(0, qex_c, qt_c, bm_c);

    for (int c = 0; c < NCHV; ++c) {
        int sn = (c + 1) % 3;
        if (c + 1 < NCHV) {
            __syncthreads();               // all warps done with current tile
            LOAD_TILE(c + 1);
            __syncthreads();
            SCAN_SLOT(sn, qex_n, qt_n, bm_n);
        } else {
            S0[wp][sn][lane + 1] = 0.f; S1[wp][sn][lane + 1] = 0.f;
            G0[wp][sn][lane + 1] = 0.f; G1[wp][sn][lane + 1] = 0.f;
            if (lane == 0) { S0[wp][sn][0] = 0.f; S1[wp][sn][0] = 0.f;
                             G0[wp][sn][0] = 0.f; G1[wp][sn][0] = 0.f; }
            qex_n = 1.f; qt_n = 1.f; bm_n = 0u;
            __syncwarp();
        }

        int sp = (c + 2) % 3, sc = c % 3;
        unsigned u = __funnelshift_r(bm_p, bm_c, lane);            // alive[j-32..j-1]
        int lim0 = __clz(~u);
        unsigned v = (lane == 31) ? bm_n : __funnelshift_r(bm_c, bm_n, lane + 1);
        unsigned nv = ~v;
        int lim1 = nv ? (__ffs(nv) - 1) : 32;

        int l0c = min(lim0, lane);      int ex0 = lim0 - l0c;
        int l1c = min(lim1, 31 - lane); int ex1 = lim1 - l1c;

        float sum = (S0[wp][sc][lane] - S0[wp][sc][lane - l0c])
                  + (S1[wp][sc][lane + 1 + l1c] - S1[wp][sc][lane + 1]);
        float sg  = (G0[wp][sc][lane] - G0[wp][sc][lane - l0c])
                  + (G1[wp][sc][lane + 1 + l1c] - G1[wp][sc][lane + 1]);
        if (ex0 > 0) {
            sum += qt_p * (S0[wp][sp][32] - S0[wp][sp][32 - ex0]);
            sg  += G0[wp][sp][32] - G0[wp][sp][32 - ex0];
        }
        if (ex1 > 0) {
            sum += __fdividef(S1[wp][sn][ex1], qt_c);
            sg  += G1[wp][sn][ex1];
        }
        ST[lane][wp] = make_float2(sg, qex_c * sum);
        __syncthreads();
        PV[((size_t)b * H_ + c * 32 + hl) * W_ + w0 + wl] = ST[hl][wl];
        __syncthreads();

        bm_p = bm_c; bm_c = bm_n; qt_p = qt_c; qt_c = qt_n; qex_c = qex_n;
    }
#undef LOAD_TILE
#undef SCAN_SLOT
}

// ---------------------------------------------------------------------------
// Horizontal O(1) scan: 16 warps scan 16 chunks (14 interior + 2 halo) of one
// row from raw inputs; warps 1..14 then resolve THEIR OWN chunk (din, alive
// ballot, qex already in registers), combine PV, blend, write.
// ---------------------------------------------------------------------------
__global__ void __launch_bounds__(512)
hscan_kernel(const float* __restrict__ pred_log,
             const int*   __restrict__ mask,
             const float* __restrict__ var,
             const float* __restrict__ depthin,
             const float* __restrict__ lam_p,
             float*       __restrict__ out)
{
    __shared__ float S0[NWARPS][33], S1[NWARPS][33], G0[NWARPS][33], G1[NWARPS][33];
    __shared__ float QT[NWARPS];
    __shared__ unsigned BMs[NWARPS];

    const int row  = blockIdx.y;            // b*H_ + h
    const int b    = row / H_;
    const int span = blockIdx.x;
    const int lane = threadIdx.x, k = threadIdx.y;
    const int c = span * SPAN + k - 1;      // this warp's chunk

    const size_t rowoff  = (size_t)row * W_;
    const size_t inplane = rowoff - (size_t)b * PLANE;

    float e0 = 1.f, g0 = 0.f, g1 = 0.f, d = 0.f;
    if (c >= 0 && c < NCHUNK) {
        int col = c * 32 + lane;
        size_t p = inplane + col;
        float ph = pred_log[(size_t)b * 2 * PLANE + p];
        float m  = mask[rowoff + col] ? 1.f : 0.f;
        float v0 = var[(size_t)b * 4 * PLANE + p];
        float v1 = var[(size_t)b * 4 * PLANE + PLANE + p];
        d  = depthin[rowoff + col];
        e0 = __expf(ph);
        g0 = __expf(-fminf(v0, 5.f)) * m;
        g1 = __expf(-fminf(v1, 5.f)) * m;
    }
    unsigned bm = __ballot_sync(0xFFFFFFFFu, g0 > 0.f);

    float q = e0;
    #pragma unroll
    for (int dd = 1; dd < 32; dd <<= 1) {
        float o = __shfl_up_sync(0xFFFFFFFFu, q, dd);
        if (lane >= dd) q *= o;
    }
    float qtot = __shfl_sync(0xFFFFFFFFu, q, 31);
    float qex  = __shfl_up_sync(0xFFFFFFFFu, q, 1);
    if (lane == 0) qex = 1.f;
    float rq = __fdividef(1.f, qex);

    S0[k][lane + 1] = wsum(g0 * d * rq, lane);
    S1[k][lane + 1] = wsum(g1 * d * rq, lane);
    G0[k][lane + 1] = wsum(g0, lane);
    G1[k][lane + 1] = wsum(g1, lane);
    if (lane == 0) {
        S0[k][0] = 0.f; S1[k][0] = 0.f; G0[k][0] = 0.f; G1[k][0] = 0.f;
        QT[k] = qtot;  BMs[k] = bm;
    }
    __syncthreads();

    // pixel phase: warps 1..SPAN resolve the chunk they scanned
    if (k < 1 || k > SPAN) return;
    if (c >= NCHUNK) return;
    const int s  = k;
    const int jl = lane;
    const size_t idx = rowoff + c * 32 + jl;

    if (!((bm >> jl) & 1u)) { out[idx] = d; return; }   // masked pixel

    float2 pv = PV[idx];
    unsigned bmp = BMs[s - 1], bmn = BMs[s + 1];
    unsigned u = __funnelshift_r(bmp, bm, jl);
    int lim0 = __clz(~u);
    unsigned v = (jl == 31) ? bmn : __funnelshift_r(bm, bmn, jl + 1);
    unsigned nv = ~v;
    int lim1 = nv ? (__ffs(nv) - 1) : 32;

    int l0c = min(lim0, jl);        int ex0 = lim0 - l0c;
    int l1c = min(lim1, 31 - jl);   int ex1 = lim1 - l1c;

    float aw  = pv.x;
    float awd = pv.y;

    float sum = S0[s][jl] - S0[s][jl - l0c];
    float sg  = G0[s][jl] - G0[s][jl - l0c];
    if (ex0 > 0) {
        sum += QT[s - 1] * (S0[s - 1][32] - S0[s - 1][32 - ex0]);
        sg  += G0[s - 1][32] - G0[s - 1][32 - ex0];
    }
    sum += S1[s][jl + 1 + l1c] - S1[s][jl + 1];
    sg  += G1[s][jl + 1 + l1c] - G1[s][jl + 1];
    if (ex1 > 0) {
        sum += __fdividef(S1[s + 1][ex1], QT[s]);
        sg  += G1[s + 1][ex1];
    }
    aw  += sg;
    awd += qex * sum;

    float o = d;
    if (aw > 0.f) {
        float lat = awd / fmaxf(aw, 1e-12f);
        if (lat > 0.f) {
            float lam = lam_p[0];
            o = d * (1.f - lam) + lat * lam;
        }
    }
    out[idx] = o;
}

extern "C" void kernel_launch(void* const* d_in, const int* in_sizes, int n_in,
                              void* d_out, int out_size)
{
    const float* pred_log = (const float*)d_in[0];
    const int*   mask     = (const int*)  d_in[1];
    const float* variance = (const float*)d_in[2];
    const float* depthin  = (const float*)d_in[3];
    const float* lam      = (const float*)d_in[4];
    float* out = (float*)d_out;

    dim3 blkv(32, 8);
    dim3 gv(W_ / 8, B_);                            // 152 x 8
    vscan_kernel<<<gv, blkv>>>(pred_log, mask, variance, depthin);

    dim3 blkh(32, NWARPS);
    dim3 gh((NCHUNK + SPAN - 1) / SPAN, B_ * H_);   // 3 x 2816
    hscan_kernel<<<gh, blkh>>>(pred_log, mask, variance, depthin, lam, out);
}

// round 17
// speedup vs baseline: 1.1095x; 1.0234x over previous
#include <cuda_runtime.h>

#define B_ 8
#define H_ 352
#define W_ 1216
#define PLANE (H_*W_)
#define NPIX (B_*PLANE)
#define NCHUNK 38                   // W_/32 horizontal chunks
#define NCHV 11                     // H_/32 vertical chunks
#define SPAN 14                     // interior chunks per hscan block
#define NWARPS 16                   // hscan warps (SPAN + 2 halo)
#define VW 16                       // vscan columns (=warps) per block

// Vertical partials (aw, awd), normal (b,h,w) layout.
__device__ float2 PV[NPIX];

__device__ __forceinline__ float wsum(float x, int lane) {
    #pragma unroll
    for (int d = 1; d < 32; d <<= 1) {
        float o = __shfl_up_sync(0xFFFFFFFFu, x, d);
        if (lane >= d) x += o;
    }
    return x;
}

// ---------------------------------------------------------------------------
// Vertical O(1) scan. Block = 16 warps x 16 adjacent columns (512 threads).
// 2-barrier pipeline with look-ahead 2:
//   iter c: resolve c -> ST | bar | PV write + load tile c+2 | bar | scan c+2
// S arrays are warp-private (slot (c+2)%3 holds chunk c-1 during resolve,
// then is re-scanned for chunk c+2 by the same warp after the resolve).
// ---------------------------------------------------------------------------
__global__ void __launch_bounds__(512)
vscan_kernel(const float* __restrict__ pred_log,
             const int*   __restrict__ mask,
             const float* __restrict__ var,
             const float* __restrict__ depth)
{
    __shared__ float S0[VW][3][33], S1[VW][3][33], G0[VW][3][33], G1[VW][3][33];
    __shared__ float s_e[32][VW+1], s_g2[32][VW+1], s_gd2[32][VW+1],
                     s_g3[32][VW+1], s_gd3[32][VW+1];
    __shared__ float s_aw[32][VW+1], s_awd[32][VW+1];

    const int lane = threadIdx.x, wp = threadIdx.y;
    const int t  = wp * 32 + lane;
    const int hl = t >> 4, wl = t & 15;         // tile-load coords (32h x 16w)
    const int b  = blockIdx.y, w0 = blockIdx.x * VW;

    const float* pvp = pred_log + (size_t)b * 2 * PLANE + PLANE;
    const float* v2p = var   + (size_t)b * 4 * PLANE + 2 * PLANE;
    const float* v3p = var   + (size_t)b * 4 * PLANE + 3 * PLANE;
    const float* dp  = depth + (size_t)b * PLANE;
    const int*   mp  = mask  + (size_t)b * PLANE;

#define ZERO_SLOT(sl) do {                                               \
        S0[wp][sl][lane + 1] = 0.f; S1[wp][sl][lane + 1] = 0.f;          \
        G0[wp][sl][lane + 1] = 0.f; G1[wp][sl][lane + 1] = 0.f;          \
        if (lane == 0) { S0[wp][sl][0] = 0.f; S1[wp][sl][0] = 0.f;       \
                         G0[wp][sl][0] = 0.f; G1[wp][sl][0] = 0.f; }     \
        __syncwarp();                                                    \
    } while (0)

#define LOAD_TILE(c) do {                                   \
        size_t p = (size_t)((c) * 32 + hl) * W_ + w0 + wl;  \
        float pv = pvp[p];                                  \
        float m  = mp[p] ? 1.f : 0.f;                       \
        float g2 = __expf(-fminf(v2p[p], 5.f)) * m;         \
        float g3 = __expf(-fminf(v3p[p], 5.f)) * m;         \
        float dd = dp[p];                                   \
        s_e [hl][wl] = __expf(pv);                          \
        s_g2[hl][wl] = g2;  s_gd2[hl][wl] = g2 * dd;        \
        s_g3[hl][wl] = g3;  s_gd3[hl][wl] = g3 * dd;        \
    } while (0)

#define SCAN_SLOT(sl, QEX, QT, BM) do {                                  \
        float e  = s_e [lane][wp];                                       \
        float ga = s_g2[lane][wp], gda = s_gd2[lane][wp];                \
        float gb = s_g3[lane][wp], gdb = s_gd3[lane][wp];                \
        BM = __ballot_sync(0xFFFFFFFFu, ga > 0.f);                       \
        float q = e;                                                     \
        _Pragma("unroll")                                                \
        for (int dd = 1; dd < 32; dd <<= 1) {                            \
            float o = __shfl_up_sync(0xFFFFFFFFu, q, dd);                \
            if (lane >= dd) q *= o;                                      \
        }                                                                \
        QT  = __shfl_sync(0xFFFFFFFFu, q, 31);                           \
        QEX = __shfl_up_sync(0xFFFFFFFFu, q, 1);                         \
        if (lane == 0) QEX = 1.f;                                        \
        float rq = __fdividef(1.f, QEX);                                 \
        S0[wp][sl][lane + 1] = wsum(gda * rq, lane);                     \
        S1[wp][sl][lane + 1] = wsum(gdb * rq, lane);                     \
        G0[wp][sl][lane + 1] = wsum(ga, lane);                           \
        G1[wp][sl][lane + 1] = wsum(gb, lane);                           \
        if (lane == 0) { S0[wp][sl][0] = 0.f; S1[wp][sl][0] = 0.f;       \
                         G0[wp][sl][0] = 0.f; G1[wp][sl][0] = 0.f; }     \
        __syncwarp();                                                    \
    } while (0)

    // registers: chunk c-1 (p), c (c), c+1 (n); scan fills c+2 each iter.
    float qex_c, qex_n, qt_p = 1.f, qt_c, qt_n;
    unsigned bm_p = 0u, bm_c, bm_n;

    ZERO_SLOT(2);                               // chunk -1 -> slot 2
    LOAD_TILE(0);
    __syncthreads();
    SCAN_SLOT(0, qex_c, qt_c, bm_c);            // chunk 0 -> slot 0
    __syncthreads();
    LOAD_TILE(1);
    __syncthreads();
    SCAN_SLOT(1, qex_n, qt_n, bm_n);            // chunk 1 -> slot 1

    for (int c = 0; c < NCHV; ++c) {
        // ---- resolve chunk c (slots: prev=(c+2)%3, cur=c%3, next=(c+1)%3) ----
        const int sp = (c + 2) % 3, sc = c % 3, sn = (c + 1) % 3;
        unsigned u = __funnelshift_r(bm_p, bm_c, lane);            // alive[j-32..j-1]
        int lim0 = __clz(~u);
        unsigned v = (lane == 31) ? bm_n : __funnelshift_r(bm_c, bm_n, lane + 1);
        unsigned nv = ~v;
        int lim1 = nv ? (__ffs(nv) - 1) : 32;

        int l0c = min(lim0, lane);      int ex0 = lim0 - l0c;
        int l1c = min(lim1, 31 - lane); int ex1 = lim1 - l1c;

        float sum = (S0[wp][sc][lane] - S0[wp][sc][lane - l0c])
                  + (S1[wp][sc][lane + 1 + l1c] - S1[wp][sc][lane + 1]);
        float sg  = (G0[wp][sc][lane] - G0[wp][sc][lane - l0c])
                  + (G1[wp][sc][lane + 1 + l1c] - G1[wp][sc][lane + 1]);
        if (ex0 > 0) {
            sum += qt_p * (S0[wp][sp][32] - S0[wp][sp][32 - ex0]);
            sg  += G0[wp][sp][32] - G0[wp][sp][32 - ex0];
        }
        if (ex1 > 0) {
            sum += __fdividef(S1[wp][sn][ex1], qt_c);
            sg  += G1[wp][sn][ex1];
        }
        s_aw [lane][wp] = sg;
        s_awd[lane][wp] = qex_c * sum;

        __syncthreads();   // ST ready; all warps done reading current tile

        // ---- PV write (coalesced) + load tile for chunk c+2 ----
        PV[((size_t)b * H_ + c * 32 + hl) * W_ + w0 + wl] =
            make_float2(s_aw[hl][wl], s_awd[hl][wl]);
        const int nc = c + 2;
        if (nc < NCHV) LOAD_TILE(nc);

        __syncthreads();   // tile ready; staging consumed

        // ---- scan chunk c+2 into slot (c+2)%3 (overwrites chunk c-1) ----
        float qex2 = 1.f, qt2 = 1.f;
        unsigned bm2 = 0u;
        if (nc < NCHV) {
            SCAN_SLOT(sp, qex2, qt2, bm2);
        } else if (c < NCHV - 1) {
            ZERO_SLOT(sp);
        }

        bm_p = bm_c; bm_c = bm_n; bm_n = bm2;
        qt_p = qt_c; qt_c = qt_n; qt_n = qt2;
        qex_c = qex_n; qex_n = qex2;
    }
#undef LOAD_TILE
#undef SCAN_SLOT
#undef ZERO_SLOT
}

// ---------------------------------------------------------------------------
// Horizontal O(1) scan (R16-proven): 16 warps scan 16 chunks (14 interior +
// 2 halo) of one row; warps 1..14 resolve their own chunk, combine PV, blend.
// ---------------------------------------------------------------------------
__global__ void __launch_bounds__(512)
hscan_kernel(const float* __restrict__ pred_log,
             const int*   __restrict__ mask,
             const float* __restrict__ var,
             const float* __restrict__ depthin,
             const float* __restrict__ lam_p,
             float*       __restrict__ out)
{
    __shared__ float S0[NWARPS][33], S1[NWARPS][33], G0[NWARPS][33], G1[NWARPS][33];
    __shared__ float QT[NWARPS];
    __shared__ unsigned BMs[NWARPS];

    const int row  = blockIdx.y;            // b*H_ + h
    const int b    = row / H_;
    const int span = blockIdx.x;
    const int lane = threadIdx.x, k = threadIdx.y;
    const int c = span * SPAN + k - 1;      // this warp's chunk

    const size_t rowoff  = (size_t)row * W_;
    const size_t inplane = rowoff - (size_t)b * PLANE;

    float e0 = 1.f, g0 = 0.f, g1 = 0.f, d = 0.f;
    if (c >= 0 && c < NCHUNK) {
        int col = c * 32 + lane;
        size_t p = inplane + col;
        float ph = pred_log[(size_t)b * 2 * PLANE + p];
        float m  = mask[rowoff + col] ? 1.f : 0.f;
        float v0 = var[(size_t)b * 4 * PLANE + p];
        float v1 = var[(size_t)b * 4 * PLANE + PLANE + p];
        d  = depthin[rowoff + col];
        e0 = __expf(ph);
        g0 = __expf(-fminf(v0, 5.f)) * m;
        g1 = __expf(-fminf(v1, 5.f)) * m;
    }
    unsigned bm = __ballot_sync(0xFFFFFFFFu, g0 > 0.f);

    float q = e0;
    #pragma unroll
    for (int dd = 1; dd < 32; dd <<= 1) {
        float o = __shfl_up_sync(0xFFFFFFFFu, q, dd);
        if (lane >= dd) q *= o;
    }
    float qtot = __shfl_sync(0xFFFFFFFFu, q, 31);
    float qex  = __shfl_up_sync(0xFFFFFFFFu, q, 1);
    if (lane == 0) qex = 1.f;
    float rq = __fdividef(1.f, qex);

    S0[k][lane + 1] = wsum(g0 * d * rq, lane);
    S1[k][lane + 1] = wsum(g1 * d * rq, lane);
    G0[k][lane + 1] = wsum(g0, lane);
    G1[k][lane + 1] = wsum(g1, lane);
    if (lane == 0) {
        S0[k][0] = 0.f; S1[k][0] = 0.f; G0[k][0] = 0.f; G1[k][0] = 0.f;
        QT[k] = qtot;  BMs[k] = bm;
    }
    __syncthreads();

    if (k < 1 || k > SPAN) return;
    if (c >= NCHUNK) return;
    const int s  = k;
    const int jl = lane;
    const size_t idx = rowoff + c * 32 + jl;

    if (!((bm >> jl) & 1u)) { out[idx] = d; return; }

    float2 pv = PV[idx];
    unsigned bmp = BMs[s - 1], bmn = BMs[s + 1];
    unsigned u = __funnelshift_r(bmp, bm, jl);
    int lim0 = __clz(~u);
    unsigned v = (jl == 31) ? bmn : __funnelshift_r(bm, bmn, jl + 1);
    unsigned nv = ~v;
    int lim1 = nv ? (__ffs(nv) - 1) : 32;

    int l0c = min(lim0, jl);        int ex0 = lim0 - l0c;
    int l1c = min(lim1, 31 - jl);   int ex1 = lim1 - l1c;

    float aw  = pv.x;
    float awd = pv.y;

    float sum = S0[s][jl] - S0[s][jl - l0c];
    float sg  = G0[s][jl] - G0[s][jl - l0c];
    if (ex0 > 0) {
        sum += QT[s - 1] * (S0[s - 1][32] - S0[s - 1][32 - ex0]);
        sg  += G0[s - 1][32] - G0[s - 1][32 - ex0];
    }
    sum += S1[s][jl + 1 + l1c] - S1[s][jl + 1];
    sg  += G1[s][jl + 1 + l1c] - G1[s][jl + 1];
    if (ex1 > 0) {
        sum += __fdividef(S1[s + 1][ex1], QT[s]);
        sg  += G1[s + 1][ex1];
    }
    aw  += sg;
    awd += qex * sum;

    float o = d;
    if (aw > 0.f) {
        float lat = awd / fmaxf(aw, 1e-12f);
        if (lat > 0.f) {
            float lam = lam_p[0];
            o = d * (1.f - lam) + lat * lam;
        }
    }
    out[idx] = o;
}

extern "C" void kernel_launch(void* const* d_in, const int* in_sizes, int n_in,
                              void* d_out, int out_size)
{
    const float* pred_log = (const float*)d_in[0];
    const int*   mask     = (const int*)  d_in[1];
    const float* variance = (const float*)d_in[2];
    const float* depthin  = (const float*)d_in[3];
    const float* lam      = (const float*)d_in[4];
    float* out = (float*)d_out;

    dim3 blkv(32, VW);
    dim3 gv(W_ / VW, B_);                           // 76 x 8
    vscan_kernel<<<gv, blkv>>>(pred_log, mask, variance, depthin);

    dim3 blkh(32, NWARPS);
    dim3 gh((NCHUNK + SPAN - 1) / SPAN, B_ * H_);   // 3 x 2816
    hscan_kernel<<<gh, blkh>>>(pred_log, mask, variance, depthin, lam, out);
}